// round 16
// baseline (speedup 1.0000x reference)
#include <cuda_runtime.h>
#include <cuda_fp16.h>
#include <cstdint>

// ---------------- problem constants ----------------
#define BB 8
#define CC 512
#define OO 512
#define HH 64
#define WW 64
#define MOD_SCALE_F 0.04419417382415922f   // 1/sqrt(512)

// padded flat grid: width 66, height 66 (1-pixel halo)
#define WP 66
#define QTOT (WP * 66)        // 4356
#define NQT 66                // q tiles of 64 covering [67, 4291) exactly
#define NTW 64
#define ROWSB 198             // 64 + 2*67 halo rows
#define NWIN 144              // 16 c-chunks * 9 taps
#define THREADS 256

// SMEM word (b32) offsets, row stride 20 b32 (80 B, bank-coprime)
#define SROW 20
#define SA0 0
#define SA1 2560                       // 128*20
#define SB0 5120
#define SB1 (SB0 + ROWSB * SROW)       // 9080
#define SMEM_DYN ((SB1 + ROWSB * SROW) * 4)   // 52160 B

// ---------------- device scratch ----------------
__device__ float    d_s[BB * CC];
__device__ float    d_W2[OO * CC];
__device__ float    d_g[BB * OO];
__device__ __half   d_xsph[(size_t)BB * QTOT * CC];        // padded NHWC fp16
__device__ uint32_t d_Wp2u[(size_t)9 * 16 * 512 * 16];     // [t][j][o][c-pair] half2

__device__ __forceinline__ void mma16816(float* d, uint32_t a0, uint32_t a1,
                                         uint32_t a2, uint32_t a3,
                                         uint32_t b0, uint32_t b1) {
    asm volatile(
        "mma.sync.aligned.m16n8k16.row.col.f32.f16.f16.f32 "
        "{%0,%1,%2,%3}, {%4,%5,%6,%7}, {%8,%9}, {%0,%1,%2,%3};"
        : "+f"(d[0]), "+f"(d[1]), "+f"(d[2]), "+f"(d[3])
        : "r"(a0), "r"(a1), "r"(a2), "r"(a3), "r"(b0), "r"(b1));
}

__device__ __forceinline__ void ldsm_x4(uint32_t& r0, uint32_t& r1,
                                        uint32_t& r2, uint32_t& r3, uint32_t addr) {
    asm volatile("ldmatrix.sync.aligned.m8n8.x4.shared.b16 {%0,%1,%2,%3}, [%4];"
                 : "=r"(r0), "=r"(r1), "=r"(r2), "=r"(r3) : "r"(addr));
}

__device__ __forceinline__ uint32_t smem_u32(const void* p) {
    uint32_t a;
    asm("{ .reg .u64 t; cvta.to.shared.u64 t, %1; cvt.u32.u64 %0, t; }" : "=r"(a) : "l"(p));
    return a;
}

// 16B async copy with zero-fill predicate (src_size = 16 or 0)
__device__ __forceinline__ void cp16(uint32_t dst, const void* src, uint32_t sz) {
    asm volatile("cp.async.cg.shared.global [%0], [%1], 16, %2;"
                 :: "r"(dst), "l"(src), "r"(sz) : "memory");
}
#define CP_COMMIT() asm volatile("cp.async.commit_group;" ::: "memory")
#define CP_WAIT0()  asm volatile("cp.async.wait_group 0;" ::: "memory")

// ---------------- stage 1: fused prep — wpack(+W2) and s[b,c] ----------------
__global__ void prep_kernel(const float* __restrict__ bw,
                            const float* __restrict__ w,
                            const float* __restrict__ mw,
                            const float* __restrict__ mb) {
    __shared__ float sm[8][289];
    int tid = threadIdx.x;
    int bx = blockIdx.x;
    if (bx < 1024) {
        int o0 = (bx & 63) * 8, j = bx >> 6;
        #pragma unroll
        for (int k = tid; k < 8 * 288; k += 256) {
            int o = k / 288, r = k - o * 288;
            sm[o][r] = bw[((size_t)(o0 + o) * 512 + j * 32) * 9 + r];
        }
        __syncthreads();
        {
            int o = tid >> 5, cl = tid & 31;
            float a = 0.f;
            #pragma unroll
            for (int t = 0; t < 9; t++) { float v = sm[o][cl * 9 + t]; a = fmaf(v, v, a); }
            d_W2[(size_t)(o0 + o) * CC + j * 32 + cl] = a;
        }
        #pragma unroll
        for (int k = tid; k < 1152; k += 256) {
            int ww = k & 15, o = (k >> 4) & 7, t = k >> 7;
            __half2 h = __floats2half2_rn(sm[o][(2 * ww) * 9 + t], sm[o][(2 * ww + 1) * 9 + t]);
            d_Wp2u[((size_t)(t * 16 + j) * 512 + o0 + o) * 16 + ww] = *(uint32_t*)&h;
        }
    } else {
        int gid = (bx - 1024) * 256 + tid;
        int wid = gid >> 5, lane = gid & 31;
        int b = wid >> 9, c = wid & 511;
        const float* wr = w + b * 512;
        const float* mr = mw + c * 512;
        float acc = 0.f;
        #pragma unroll 4
        for (int d = lane; d < 512; d += 32) acc = fmaf(wr[d], mr[d], acc);
        #pragma unroll
        for (int o = 16; o; o >>= 1) acc += __shfl_xor_sync(0xffffffffu, acc, o);
        if (lane == 0) d_s[wid] = acc * MOD_SCALE_F + mb[c] + 1.0f;
    }
}

// ---------------- stage 2: g[b,o] ----------------
__global__ void g_kernel() {
    int gid = blockIdx.x * blockDim.x + threadIdx.x;
    int wid = gid >> 5, lane = gid & 31;
    if (wid >= BB * OO) return;
    int b = wid >> 9, o = wid & 511;
    const float* sr = d_s + b * 512;
    const float* w2 = d_W2 + o * 512;
    float acc = 0.f;
    #pragma unroll 4
    for (int c = lane; c < 512; c += 32) { float sv = sr[c]; acc = fmaf(sv * sv, w2[c], acc); }
    #pragma unroll
    for (int o2 = 16; o2; o2 >>= 1) acc += __shfl_xor_sync(0xffffffffu, acc, o2);
    if (lane == 0) d_g[wid] = rsqrtf(acc);
}

// ---------------- stage 3: modulated NCHW -> padded NHWC fp16 + pad-zero -----
__global__ void xspad_kernel(const float* __restrict__ x) {
    __shared__ float t[2][32][65];
    __shared__ float ss[32];
    int tid = threadIdx.x;
    int b = blockIdx.z;
    if (blockIdx.x == 16) {
        int base = blockIdx.y * 256 + tid;
        #pragma unroll
        for (int k = 0; k < 3; k++) {
            int u = base + k * 8192;
            if (u < 260 * 64) {
                int p = u >> 6, f = u & 63;
                int q;
                if (p < 66) q = p;
                else if (p < 132) q = 65 * WP + (p - 66);
                else { int p2 = p - 132; q = (1 + (p2 >> 1)) * WP + ((p2 & 1) ? 65 : 0); }
                ((uint4*)d_xsph)[((size_t)b * QTOT + q) * 64 + f] =
                    make_uint4(0u, 0u, 0u, 0u);
            }
        }
        return;
    }
    int h0 = blockIdx.y * 2, c0 = blockIdx.x * 32;
    if (tid < 32) ss[tid] = d_s[b * CC + c0 + tid];
    __syncthreads();
    #pragma unroll
    for (int k = 0; k < 4; k++) {
        int idx = tid + k * 256;
        int hh = idx >> 9;
        int r = idx & 511;
        int c = r >> 4, w4 = (r & 15) * 4;
        float4 v = *(const float4*)&x[(((size_t)b * CC + c0 + c) * HH + h0 + hh) * WW + w4];
        float sc = ss[c];
        t[hh][c][w4]     = v.x * sc;
        t[hh][c][w4 + 1] = v.y * sc;
        t[hh][c][w4 + 2] = v.z * sc;
        t[hh][c][w4 + 3] = v.w * sc;
    }
    __syncthreads();
    #pragma unroll
    for (int k = 0; k < 2; k++) {
        int idx = tid + k * 256;
        int hh = idx >> 8;
        int r = idx & 255;
        int w = r >> 2, cg = r & 3;
        __half h8[8];
        #pragma unroll
        for (int q = 0; q < 8; q++) h8[q] = __float2half_rn(t[hh][cg * 8 + q][w]);
        *(uint4*)&d_xsph[((size_t)b * QTOT + (h0 + hh + 1) * WP + (w + 1)) * CC + c0 + cg * 8] =
            *(uint4*)h8;
    }
}

// ---------------- stage 4: fp16 mma.sync conv, 128x64 tile, 3 CTAs/SM --------
__global__ __launch_bounds__(THREADS, 3) void conv_mma_kernel(float* __restrict__ out) {
    extern __shared__ uint32_t smem_u[];
    const uint32_t sbase = smem_u32(smem_u);
    const int tid = threadIdx.x;
    const int wid = tid >> 5, lane = tid & 31;
    const int mw = wid & 3, nw = wid >> 2;     // o-quarter (4), q-half (2)
    const int tile = blockIdx.x, og = blockIdx.y, b = blockIdx.z;
    const int q0 = 67 + NTW * tile;
    const int qb = q0 - 67;
    const int o0 = og * 128;

    const int DT[9] = {-67, -66, -65, -1, 0, 1, 65, 66, 67};

    const int aRowOff = (lane & 15) * 80 + (lane >> 4) * 16;
    const int bRowOff = ((lane & 7) + ((lane & 16) >> 1)) * 80 + ((lane & 8) << 1);

    float acc[2][4][4];
    #pragma unroll
    for (int mt = 0; mt < 2; mt++)
        #pragma unroll
        for (int nt = 0; nt < 4; nt++)
            #pragma unroll
            for (int r = 0; r < 4; r++) acc[mt][nt][r] = 0.f;

    const char* xBb = (const char*)(d_xsph + (size_t)b * QTOT * CC);
    const char* wBb = (const char*)d_Wp2u;

    // ---- A window stage (1 tap): 512 units = (row<128, seg<4), 2/thread ----
    auto stageA = [&](int u, int jn, int tn) {
        const uint32_t dstBase = sbase + ((u & 1) ? SA1 : SA0) * 4;
        #pragma unroll
        for (int p = 0; p < 2; p++) {
            int idx = p * THREADS + tid;
            int seg = idx & 3, row = idx >> 2;
            const void* src = wBb + (((size_t)(tn * 16 + jn) * 512 + o0 + row) << 6) + seg * 16;
            cp16(dstBase + (uint32_t)(row * SROW + seg * 4) * 4, src, 16);
        }
    };
    // ---- B partial stage: units [lo, lo+88) of chunk jB's 792 units ----
    auto stageBpart = [&](int jB, int lo) {
        const uint32_t dstBase = sbase + ((jB & 1) ? SB1 : SB0) * 4;
        if (tid < 88) {
            int g = lo + tid;
            if (g < ROWSB * 4) {
                int r = g >> 2, seg = g & 3;
                int gq = qb + r;
                uint32_t ok = (gq >= 0 && gq < QTOT) ? 16u : 0u;
                int gqc = ok ? gq : 0;
                const void* src = xBb + ((size_t)gqc * 1024) + jB * 64 + seg * 16;
                cp16(dstBase + (uint32_t)(r * SROW + seg * 4) * 4, src, ok);
            }
        }
    };

    // ---- prologue: A window 0 + full B chunk 0 ----
    stageA(0, 0, 0);
    {
        const uint32_t dstBase = sbase + SB0 * 4;
        #pragma unroll
        for (int it = 0; it < 4; it++) {
            int g = it * THREADS + tid;
            if (g < ROWSB * 4) {
                int r = g >> 2, seg = g & 3;
                int gq = qb + r;
                uint32_t ok = (gq >= 0 && gq < QTOT) ? 16u : 0u;
                int gqc = ok ? gq : 0;
                const void* src = xBb + ((size_t)gqc * 1024) + seg * 16;
                cp16(dstBase + (uint32_t)(r * SROW + seg * 4) * 4, src, ok);
            }
        }
    }
    CP_COMMIT();
    CP_WAIT0();
    __syncthreads();

    // ---- main loop: 144 windows (chunk j, tap tg) ----
    int j = 0, tg = 0;
    for (int u = 0; u < NWIN; u++) {
        const int un = u + 1;
        if (un < NWIN) {
            int jn = (tg == 8) ? j + 1 : j;
            int tn = (tg == 8) ? 0 : tg + 1;
            stageA(un, jn, tn);
        }
        if (j + 1 < 16) stageBpart(j + 1, tg * 88);
        CP_COMMIT();

        const uint32_t aBase = sbase + ((u & 1) ? SA1 : SA0) * 4 +
                               (uint32_t)(mw * 32) * 80 + aRowOff;
        const uint32_t bBase = sbase + ((j & 1) ? SB1 : SB0) * 4 +
                               (uint32_t)(67 + DT[tg] + nw * 32) * 80 + bRowOff;
        #pragma unroll
        for (int ks = 0; ks < 2; ks++) {
            uint32_t a[2][4], bfr[2][4];
            #pragma unroll
            for (int mt = 0; mt < 2; mt++)
                ldsm_x4(a[mt][0], a[mt][1], a[mt][2], a[mt][3],
                        aBase + mt * (16 * 80) + ks * 32);
            #pragma unroll
            for (int ntp = 0; ntp < 2; ntp++)
                ldsm_x4(bfr[ntp][0], bfr[ntp][1], bfr[ntp][2], bfr[ntp][3],
                        bBase + ntp * (16 * 80) + ks * 32);
            #pragma unroll
            for (int ntp = 0; ntp < 2; ntp++)
                #pragma unroll
                for (int mt = 0; mt < 2; mt++) {
                    mma16816(acc[mt][2 * ntp],     a[mt][0], a[mt][1], a[mt][2], a[mt][3],
                             bfr[ntp][0], bfr[ntp][1]);
                    mma16816(acc[mt][2 * ntp + 1], a[mt][0], a[mt][1], a[mt][2], a[mt][3],
                             bfr[ntp][2], bfr[ntp][3]);
                }
        }

        CP_WAIT0();
        __syncthreads();

        if (tg == 8) { tg = 0; j++; } else tg++;
    }

    // ---- epilogue: SMEM transpose (128 x 68), scale by g, predicated stores ----
    const int g = lane >> 2, t4 = lane & 3;
    float* eb = (float*)smem_u;
    __syncthreads();
    #pragma unroll
    for (int mt = 0; mt < 2; mt++)
        #pragma unroll
        for (int nt = 0; nt < 4; nt++) {
            int row = mw * 32 + mt * 16 + g;
            int col = nw * 32 + nt * 8 + 2 * t4;
            eb[row * 68 + col]           = acc[mt][nt][0];
            eb[row * 68 + col + 1]       = acc[mt][nt][1];
            eb[(row + 8) * 68 + col]     = acc[mt][nt][2];
            eb[(row + 8) * 68 + col + 1] = acc[mt][nt][3];
        }
    __syncthreads();
    #pragma unroll 4
    for (int it = 0; it < 32; it++) {
        int i = it * THREADS + tid;          // 128 o-local x 64 d
        int ol = i >> 6, d = i & 63;
        int q = q0 + d;
        int qr = q / WP, qc = q - qr * WP;
        if (qc >= 1 && qc <= 64 && qr <= 64) {
            int o = o0 + ol;
            float gv = d_g[b * OO + o];
            out[(((size_t)b * OO + o) * 64 + qr - 1) * 64 + qc - 1] =
                eb[ol * 68 + d] * gv;
        }
    }
}

// ---------------- launch ----------------
extern "C" void kernel_launch(void* const* d_in, const int* in_sizes, int n_in,
                              void* d_out, int out_size) {
    const float *x = nullptr, *w = nullptr, *bw = nullptr, *mw = nullptr, *mb = nullptr;
    for (int i = 0; i < n_in; i++) {
        switch (in_sizes[i]) {
            case BB * CC * HH * WW: x  = (const float*)d_in[i]; break;
            case BB * 512:          w  = (const float*)d_in[i]; break;
            case OO * CC * 9:       bw = (const float*)d_in[i]; break;
            case OO * CC:           mw = (const float*)d_in[i]; break;
            case CC:                mb = (const float*)d_in[i]; break;
        }
    }
    float* out = (float*)d_out;

    cudaFuncSetAttribute(conv_mma_kernel, cudaFuncAttributeMaxDynamicSharedMemorySize, SMEM_DYN);

    prep_kernel<<<1536, 256>>>(bw, w, mw, mb);      // wpack + W2 + s
    g_kernel<<<(BB * OO * 32 + 255) / 256, 256>>>();
    xspad_kernel<<<dim3(17, 32, 8), 256>>>(x);      // transpose + pad-zero
    conv_mma_kernel<<<dim3(NQT, 4, BB), THREADS, SMEM_DYN>>>(out);
}

// round 17
// speedup vs baseline: 1.2381x; 1.2381x over previous
#include <cuda_runtime.h>
#include <cuda_fp16.h>
#include <cstdint>

// ---------------- problem constants ----------------
#define BB 8
#define CC 512
#define OO 512
#define HH 64
#define WW 64
#define MOD_SCALE_F 0.04419417382415922f   // 1/sqrt(512)

// padded flat grid: width 66, height 66 (1-pixel halo)
#define WP 66
#define QTOT (WP * 66)        // 4356
#define NQT 33                // q tiles of 128 covering [67, 4291) exactly
#define NTW 128
#define ROWSB 262             // 128 + 2*67 halo rows
#define NWIN 48               // 16 c-chunks * 3 tap-groups
#define THREADS 256

// SMEM word (b32) offsets, row stride 20 b32 (80 B, bank-coprime)
#define SROW 20
#define SA0 0
#define SA1 7680                       // 3*128*20
#define SB0 15360
#define SB1 (SB0 + ROWSB * SROW)       // 20600
#define SMEM_DYN ((SB1 + ROWSB * SROW) * 4)   // 103360 B

// ---------------- device scratch ----------------
__device__ float    d_s[BB * CC];
__device__ float    d_W2[OO * CC];
__device__ float    d_g[BB * OO];
__device__ __half   d_xsph[(size_t)BB * QTOT * CC];        // padded NHWC fp16
__device__ uint32_t d_Wp2u[(size_t)9 * 16 * 512 * 16];     // [t][j][o][c-pair] half2

__device__ __forceinline__ void mma16816(float* d, uint32_t a0, uint32_t a1,
                                         uint32_t a2, uint32_t a3,
                                         uint32_t b0, uint32_t b1) {
    asm volatile(
        "mma.sync.aligned.m16n8k16.row.col.f32.f16.f16.f32 "
        "{%0,%1,%2,%3}, {%4,%5,%6,%7}, {%8,%9}, {%0,%1,%2,%3};"
        : "+f"(d[0]), "+f"(d[1]), "+f"(d[2]), "+f"(d[3])
        : "r"(a0), "r"(a1), "r"(a2), "r"(a3), "r"(b0), "r"(b1));
}

__device__ __forceinline__ void ldsm_x4(uint32_t& r0, uint32_t& r1,
                                        uint32_t& r2, uint32_t& r3, uint32_t addr) {
    asm volatile("ldmatrix.sync.aligned.m8n8.x4.shared.b16 {%0,%1,%2,%3}, [%4];"
                 : "=r"(r0), "=r"(r1), "=r"(r2), "=r"(r3) : "r"(addr));
}

__device__ __forceinline__ uint32_t smem_u32(const void* p) {
    uint32_t a;
    asm("{ .reg .u64 t; cvta.to.shared.u64 t, %1; cvt.u32.u64 %0, t; }" : "=r"(a) : "l"(p));
    return a;
}

// 16B async copy with zero-fill predicate (src_size = 16 or 0)
__device__ __forceinline__ void cp16(uint32_t dst, const void* src, uint32_t sz) {
    asm volatile("cp.async.cg.shared.global [%0], [%1], 16, %2;"
                 :: "r"(dst), "l"(src), "r"(sz) : "memory");
}
#define CP_COMMIT() asm volatile("cp.async.commit_group;" ::: "memory")
#define CP_WAIT0()  asm volatile("cp.async.wait_group 0;" ::: "memory")

// ---------------- stage 1: fused prep — wpack(+W2) and s[b,c] ----------------
// blocks [0,1024): wpack (o-tile of 8, j) + W2 byproduct
// blocks [1024,1536): s[b,c]
__global__ void prep_kernel(const float* __restrict__ bw,
                            const float* __restrict__ w,
                            const float* __restrict__ mw,
                            const float* __restrict__ mb) {
    __shared__ float sm[8][289];
    int tid = threadIdx.x;
    int bx = blockIdx.x;
    if (bx < 1024) {
        int o0 = (bx & 63) * 8, j = bx >> 6;
        #pragma unroll
        for (int k = tid; k < 8 * 288; k += 256) {
            int o = k / 288, r = k - o * 288;
            sm[o][r] = bw[((size_t)(o0 + o) * 512 + j * 32) * 9 + r];
        }
        __syncthreads();
        {
            int o = tid >> 5, cl = tid & 31;
            float a = 0.f;
            #pragma unroll
            for (int t = 0; t < 9; t++) { float v = sm[o][cl * 9 + t]; a = fmaf(v, v, a); }
            d_W2[(size_t)(o0 + o) * CC + j * 32 + cl] = a;
        }
        #pragma unroll
        for (int k = tid; k < 1152; k += 256) {
            int ww = k & 15, o = (k >> 4) & 7, t = k >> 7;
            __half2 h = __floats2half2_rn(sm[o][(2 * ww) * 9 + t], sm[o][(2 * ww + 1) * 9 + t]);
            d_Wp2u[((size_t)(t * 16 + j) * 512 + o0 + o) * 16 + ww] = *(uint32_t*)&h;
        }
    } else {
        int gid = (bx - 1024) * 256 + tid;
        int wid = gid >> 5, lane = gid & 31;
        int b = wid >> 9, c = wid & 511;
        const float* wr = w + b * 512;
        const float* mr = mw + c * 512;
        float acc = 0.f;
        #pragma unroll 4
        for (int d = lane; d < 512; d += 32) acc = fmaf(wr[d], mr[d], acc);
        #pragma unroll
        for (int o = 16; o; o >>= 1) acc += __shfl_xor_sync(0xffffffffu, acc, o);
        if (lane == 0) d_s[wid] = acc * MOD_SCALE_F + mb[c] + 1.0f;
    }
}

// ---------------- stage 2: xspad (transpose + pad-zero) + fused g[b,o] -------
// grid (18, 32, 8): x<16 transpose 2 h-rows; x==16 pad-zero; x==17 compute g
// (prep has completed in stream order, so d_s and d_W2 are ready)
__global__ void xspad_kernel(const float* __restrict__ x) {
    __shared__ float t[2][32][65];
    __shared__ float ss[32];
    int tid = threadIdx.x;
    int b = blockIdx.z;
    if (blockIdx.x == 17) {
        // g: 256 blocks x 8 warps = 2048 warps; 2 (b,o) pairs each
        int wg = ((b * 32 + blockIdx.y) * 8) + (tid >> 5);
        int lane = tid & 31;
        #pragma unroll
        for (int pi = 0; pi < 2; pi++) {
            int p = wg * 2 + pi;                 // 0..4095
            int bp = p >> 9, o = p & 511;
            const float* sr = d_s + bp * 512;
            const float* w2 = d_W2 + (size_t)o * 512;
            float acc = 0.f;
            #pragma unroll 4
            for (int c = lane; c < 512; c += 32) {
                float sv = sr[c];
                acc = fmaf(sv * sv, w2[c], acc);
            }
            #pragma unroll
            for (int o2 = 16; o2; o2 >>= 1) acc += __shfl_xor_sync(0xffffffffu, acc, o2);
            if (lane == 0) d_g[p] = rsqrtf(acc);
        }
        return;
    }
    if (blockIdx.x == 16) {
        int base = blockIdx.y * 256 + tid;
        #pragma unroll
        for (int k = 0; k < 3; k++) {
            int u = base + k * 8192;
            if (u < 260 * 64) {
                int p = u >> 6, f = u & 63;
                int q;
                if (p < 66) q = p;
                else if (p < 132) q = 65 * WP + (p - 66);
                else { int p2 = p - 132; q = (1 + (p2 >> 1)) * WP + ((p2 & 1) ? 65 : 0); }
                ((uint4*)d_xsph)[((size_t)b * QTOT + q) * 64 + f] =
                    make_uint4(0u, 0u, 0u, 0u);
            }
        }
        return;
    }
    int h0 = blockIdx.y * 2, c0 = blockIdx.x * 32;
    if (tid < 32) ss[tid] = d_s[b * CC + c0 + tid];
    __syncthreads();
    #pragma unroll
    for (int k = 0; k < 4; k++) {
        int idx = tid + k * 256;
        int hh = idx >> 9;
        int r = idx & 511;
        int c = r >> 4, w4 = (r & 15) * 4;
        float4 v = *(const float4*)&x[(((size_t)b * CC + c0 + c) * HH + h0 + hh) * WW + w4];
        float sc = ss[c];
        t[hh][c][w4]     = v.x * sc;
        t[hh][c][w4 + 1] = v.y * sc;
        t[hh][c][w4 + 2] = v.z * sc;
        t[hh][c][w4 + 3] = v.w * sc;
    }
    __syncthreads();
    #pragma unroll
    for (int k = 0; k < 2; k++) {
        int idx = tid + k * 256;
        int hh = idx >> 8;
        int r = idx & 255;
        int w = r >> 2, cg = r & 3;
        __half h8[8];
        #pragma unroll
        for (int q = 0; q < 8; q++) h8[q] = __float2half_rn(t[hh][cg * 8 + q][w]);
        *(uint4*)&d_xsph[((size_t)b * QTOT + (h0 + hh + 1) * WP + (w + 1)) * CC + c0 + cg * 8] =
            *(uint4*)h8;
    }
}

// ---------------- stage 3: fp16 mma.sync implicit-GEMM conv, 128x128 tile ----
// (exact R14 configuration — measured best: 437 us, tensor 64%)
__global__ __launch_bounds__(THREADS, 2) void conv_mma_kernel(float* __restrict__ out) {
    extern __shared__ uint32_t smem_u[];
    const uint32_t sbase = smem_u32(smem_u);
    const int tid = threadIdx.x;
    const int wid = tid >> 5, lane = tid & 31;
    const int mw = wid & 1, nw = wid >> 1;     // o-half (2), q-warp (4)
    const int tile = blockIdx.x, og = blockIdx.y, b = blockIdx.z;
    const int q0 = 67 + NTW * tile;
    const int qb = q0 - 67;
    const int o0 = og * 128;

    const int DT[9] = {-67, -66, -65, -1, 0, 1, 65, 66, 67};

    const int aRowOff = (lane & 15) * 80 + (lane >> 4) * 16;
    const int bRowOff = ((lane & 7) + ((lane & 16) >> 1)) * 80 + ((lane & 8) << 1);

    float acc[4][4][4];
    #pragma unroll
    for (int mt = 0; mt < 4; mt++)
        #pragma unroll
        for (int nt = 0; nt < 4; nt++)
            #pragma unroll
            for (int r = 0; r < 4; r++) acc[mt][nt][r] = 0.f;

    const char* xBb = (const char*)(d_xsph + (size_t)b * QTOT * CC);
    const char* wBb = (const char*)d_Wp2u;

    // ---- A window stage: 1536 units = (tap<3, row<128, seg<4), 6/thread ----
    auto stageA = [&](int u, int jn, int tg3) {
        const uint32_t dstBase = sbase + ((u & 1) ? SA1 : SA0) * 4;
        #pragma unroll
        for (int p = 0; p < 6; p++) {
            int idx = p * THREADS + tid;
            int seg = idx & 3, row = (idx >> 2) & 127, t = idx >> 9;
            int tap = tg3 * 3 + t;
            const void* src = wBb + (((size_t)(tap * 16 + jn) * 512 + o0 + row) << 6) + seg * 16;
            cp16(dstBase + (uint32_t)(t * 2560 + row * SROW + seg * 4) * 4, src, 16);
        }
    };
    // ---- B partial stage: units [lo, lo+350) of chunk jB's 1048 units ----
    auto stageBpart = [&](int jB, int lo) {
        const uint32_t dstBase = sbase + ((jB & 1) ? SB1 : SB0) * 4;
        #pragma unroll
        for (int k = 0; k < 2; k++) {
            int rel = k * THREADS + tid;
            if (rel < 350) {
                int g = lo + rel;
                if (g < ROWSB * 4) {
                    int r = g >> 2, seg = g & 3;
                    int gq = qb + r;
                    uint32_t ok = (gq >= 0 && gq < QTOT) ? 16u : 0u;
                    int gqc = ok ? gq : 0;
                    const void* src = xBb + ((size_t)gqc * 1024) + jB * 64 + seg * 16;
                    cp16(dstBase + (uint32_t)(r * SROW + seg * 4) * 4, src, ok);
                }
            }
        }
    };

    // ---- prologue: A window 0 + full B chunk 0 ----
    stageA(0, 0, 0);
    {
        const uint32_t dstBase = sbase + SB0 * 4;
        for (int it = 0; it < 5; it++) {
            int g = it * THREADS + tid;
            if (g < ROWSB * 4) {
                int r = g >> 2, seg = g & 3;
                int gq = qb + r;
                uint32_t ok = (gq >= 0 && gq < QTOT) ? 16u : 0u;
                int gqc = ok ? gq : 0;
                const void* src = xBb + ((size_t)gqc * 1024) + seg * 16;
                cp16(dstBase + (uint32_t)(r * SROW + seg * 4) * 4, src, ok);
            }
        }
    }
    CP_COMMIT();
    CP_WAIT0();
    __syncthreads();

    // ---- main loop: 48 windows ----
    int j = 0, tg = 0;
    for (int u = 0; u < NWIN; u++) {
        const int un = u + 1;
        if (un < NWIN) {
            int jn = (tg == 2) ? j + 1 : j;
            int tgn = (tg == 2) ? 0 : tg + 1;
            stageA(un, jn, tgn);
        }
        if (j + 1 < 16) stageBpart(j + 1, tg * 350);
        CP_COMMIT();

        const uint32_t aWinBase = sbase + ((u & 1) ? SA1 : SA0) * 4 +
                                  (uint32_t)(mw * 64) * 80 + aRowOff;
        const uint32_t bChBase = sbase + ((j & 1) ? SB1 : SB0) * 4 + bRowOff;
        #pragma unroll
        for (int t = 0; t < 3; t++) {
            const int dt = DT[tg * 3 + t];
            const uint32_t aBase = aWinBase + (uint32_t)t * (2560 * 4);
            const uint32_t bBase = bChBase + (uint32_t)(67 + dt + nw * 32) * 80;
            #pragma unroll
            for (int ks = 0; ks < 2; ks++) {
                uint32_t a[4][4], bfr[2][4];
                #pragma unroll
                for (int mt = 0; mt < 4; mt++)
                    ldsm_x4(a[mt][0], a[mt][1], a[mt][2], a[mt][3],
                            aBase + mt * (16 * 80) + ks * 32);
                #pragma unroll
                for (int ntp = 0; ntp < 2; ntp++)
                    ldsm_x4(bfr[ntp][0], bfr[ntp][1], bfr[ntp][2], bfr[ntp][3],
                            bBase + ntp * (16 * 80) + ks * 32);
                #pragma unroll
                for (int ntp = 0; ntp < 2; ntp++)
                    #pragma unroll
                    for (int mt = 0; mt < 4; mt++) {
                        mma16816(acc[mt][2 * ntp],     a[mt][0], a[mt][1], a[mt][2], a[mt][3],
                                 bfr[ntp][0], bfr[ntp][1]);
                        mma16816(acc[mt][2 * ntp + 1], a[mt][0], a[mt][1], a[mt][2], a[mt][3],
                                 bfr[ntp][2], bfr[ntp][3]);
                    }
            }
        }

        CP_WAIT0();
        __syncthreads();

        if (tg == 2) { tg = 0; j++; } else tg++;
    }

    // ---- epilogue: single-pass SMEM transpose (128 x 132), scale, store ----
    const int g = lane >> 2, t4 = lane & 3;
    float* eb = (float*)smem_u;
    __syncthreads();
    #pragma unroll
    for (int mt = 0; mt < 4; mt++)
        #pragma unroll
        for (int nt = 0; nt < 4; nt++) {
            int row = mw * 64 + mt * 16 + g;
            int col = nw * 32 + nt * 8 + 2 * t4;
            eb[row * 132 + col]           = acc[mt][nt][0];
            eb[row * 132 + col + 1]       = acc[mt][nt][1];
            eb[(row + 8) * 132 + col]     = acc[mt][nt][2];
            eb[(row + 8) * 132 + col + 1] = acc[mt][nt][3];
        }
    __syncthreads();
    #pragma unroll 4
    for (int it = 0; it < 64; it++) {
        int i = it * THREADS + tid;          // 128 o-local x 128 d
        int ol = i >> 7, d = i & 127;
        int q = q0 + d;
        int qr = q / WP, qc = q - qr * WP;
        if (qc >= 1 && qc <= 64 && qr <= 64) {
            int o = o0 + ol;
            float gv = d_g[b * OO + o];
            out[(((size_t)b * OO + o) * 64 + qr - 1) * 64 + qc - 1] =
                eb[ol * 132 + d] * gv;
        }
    }
}

// ---------------- launch ----------------
extern "C" void kernel_launch(void* const* d_in, const int* in_sizes, int n_in,
                              void* d_out, int out_size) {
    const float *x = nullptr, *w = nullptr, *bw = nullptr, *mw = nullptr, *mb = nullptr;
    for (int i = 0; i < n_in; i++) {
        switch (in_sizes[i]) {
            case BB * CC * HH * WW: x  = (const float*)d_in[i]; break;
            case BB * 512:          w  = (const float*)d_in[i]; break;
            case OO * CC * 9:       bw = (const float*)d_in[i]; break;
            case OO * CC:           mw = (const float*)d_in[i]; break;
            case CC:                mb = (const float*)d_in[i]; break;
        }
    }
    float* out = (float*)d_out;

    cudaFuncSetAttribute(conv_mma_kernel, cudaFuncAttributeMaxDynamicSharedMemorySize, SMEM_DYN);

    prep_kernel<<<1536, 256>>>(bw, w, mw, mb);      // wpack + W2 + s
    xspad_kernel<<<dim3(18, 32, 8), 256>>>(x);      // transpose + pad-zero + g
    conv_mma_kernel<<<dim3(NQT, 4, BB), THREADS, SMEM_DYN>>>(out);
}